// round 5
// baseline (speedup 1.0000x reference)
#include <cuda_runtime.h>
#include <cuda_bf16.h>
#include <cstdint>

// Problem shape (fixed by dataset)
#define BB 8
#define SS 2048
#define DD 1024
#define OO 1024
#define LCH 128           // scan chunk length
#define NCH (SS / LCH)    // 16 chunks

// A' = 8*h/beta_d ; B' = beta_d*1024*BC ; out = acc / 8192
#define OUT_SCALE (1.0f / 8192.0f)
// int8 quantization scales (chosen so SA2*SB2 == SA3*SB3 -> shared s32 acc)
#define SA2 (1.0f / 1024.0f)          // H_lo quant step
#define SB2 (36.0f / 127.0f)          // C'_hi quant step
#define SA3 (46.0f / 127.0f)          // H' quant step
#define SB3 ((SA2 * SB2) / SA3)       // C'_lo quant step
#define CORR (SA2 * SB2)              // weight of int accumulator

// ---------------- device scratch (no allocations allowed) ----------------
__device__ float          g_carry[BB * NCH * DD];                 // 512 KB
__device__ __nv_bfloat16  g_hs_hi[(size_t)BB * SS * DD];          // 32 MB  bf16(H')
__device__ unsigned char  g_hs_lo8[(size_t)BB * SS * DD];         // 16 MB  s8(H'-bf16(H'))
__device__ unsigned char  g_hs_q8[(size_t)BB * SS * DD];          // 16 MB  s8(H')
__device__ __nv_bfloat16  g_bct_hi[(size_t)OO * DD];              // 2 MB   bf16(C') (BC^T)
__device__ unsigned char  g_bct_hi8[(size_t)OO * DD];             // 1 MB   s8(C')
__device__ unsigned char  g_bct_lo8[(size_t)OO * DD];             // 1 MB   s8(C'-bf16(C'))

// ---------------- helpers --------------------------------------------------
__device__ __forceinline__ uint32_t smem_u32(const void* p) {
    uint32_t a;
    asm("{ .reg .u64 t; cvta.to.shared.u64 t, %1; cvt.u32.u64 %0, t; }"
        : "=r"(a) : "l"(p));
    return a;
}

__device__ __forceinline__ int q8(float v, float inv_step) {
    int i = __float2int_rn(v * inv_step);
    return max(-127, min(127, i));
}

#define SW128(off) ((off) ^ (((off) >> 3) & 0x70))

#define CP_ASYNC_16(dst_smem, src_gmem) \
    asm volatile("cp.async.cg.shared.global [%0], [%1], 16;" \
                 :: "r"(dst_smem), "l"(src_gmem) : "memory")
#define CP_COMMIT() asm volatile("cp.async.commit_group;" ::: "memory")
#define CP_WAIT_GROUP(n) asm volatile("cp.async.wait_group %0;" :: "n"(n) : "memory")

#define LDSM_X4(r0, r1, r2, r3, addr) \
    asm volatile("ldmatrix.sync.aligned.m8n8.x4.shared.b16 {%0,%1,%2,%3}, [%4];" \
                 : "=r"(r0), "=r"(r1), "=r"(r2), "=r"(r3) : "r"(addr))

#define MMA_BF16(c, a, b) \
    asm volatile("mma.sync.aligned.m16n8k16.row.col.f32.bf16.bf16.f32 " \
                 "{%0,%1,%2,%3}, {%4,%5,%6,%7}, {%8,%9}, {%0,%1,%2,%3};" \
                 : "+f"((c)[0]), "+f"((c)[1]), "+f"((c)[2]), "+f"((c)[3]) \
                 : "r"((a)[0]), "r"((a)[1]), "r"((a)[2]), "r"((a)[3]), \
                   "r"((b)[0]), "r"((b)[1]))

#define MMA_S8(c, a, b) \
    asm volatile("mma.sync.aligned.m16n8k32.row.col.s32.s8.s8.s32 " \
                 "{%0,%1,%2,%3}, {%4,%5,%6,%7}, {%8,%9}, {%0,%1,%2,%3};" \
                 : "+r"((c)[0]), "+r"((c)[1]), "+r"((c)[2]), "+r"((c)[3]) \
                 : "r"((a)[0]), "r"((a)[1]), "r"((a)[2]), "r"((a)[3]), \
                   "r"((b)[0]), "r"((b)[1]))

// ---------------- Kernel 1: per-chunk carries (float2/thread) -------------
__global__ void scan_carry_kernel(const float* __restrict__ x,
                                  const float* __restrict__ A) {
    int idx = blockIdx.x * blockDim.x + threadIdx.x;   // B*NCH*DD/2 threads
    int d = (idx & (DD / 2 - 1)) * 2;
    int chunk = (idx >> 9) & (NCH - 1);
    int b = idx >> 13;
    float2 a = *(const float2*)(A + d);
    const float* xp = x + ((size_t)(b * SS + chunk * LCH)) * DD + d;
    float2 h = make_float2(0.0f, 0.0f);
#pragma unroll 8
    for (int i = 0; i < LCH; i++) {
        float2 xv = *(const float2*)(xp + (size_t)i * DD);
        h.x = fmaf(h.x, a.x, xv.x);
        h.y = fmaf(h.y, a.y, xv.y);
    }
    *(float2*)(g_carry + (size_t)((b * NCH + chunk) * DD) + d) = h;
}

// ---------------- Kernel 2: carry-corrected emit + quantize ---------------
__global__ void scan_emit_kernel(const float* __restrict__ x,
                                 const float* __restrict__ A) {
    int idx = blockIdx.x * blockDim.x + threadIdx.x;
    int d = (idx & (DD / 2 - 1)) * 2;
    int chunk = (idx >> 9) & (NCH - 1);
    int b = idx >> 13;
    float2 a = *(const float2*)(A + d);
    float2 aL = a;
#pragma unroll
    for (int s = 0; s < 7; s++) { aL.x *= aL.x; aL.y *= aL.y; }   // a^128
    float2 h = make_float2(0.0f, 0.0f);
    for (int j = 0; j < chunk; j++) {
        float2 cv = *(const float2*)(g_carry + (size_t)((b * NCH + j) * DD) + d);
        h.x = fmaf(h.x, aL.x, cv.x);
        h.y = fmaf(h.y, aL.y, cv.y);
    }
    // per-d normalizer: w = 8*sqrt(1-a^2) = 8/beta, so H' = h*w ~ N(0, 8^2)
    float wx = 8.0f * sqrtf(fmaf(-a.x, a.x, 1.0f));
    float wy = 8.0f * sqrtf(fmaf(-a.y, a.y, 1.0f));
    size_t base = ((size_t)(b * SS + chunk * LCH)) * DD + d;
#pragma unroll 4
    for (int i = 0; i < LCH; i++) {
        size_t off = base + (size_t)i * DD;
        float2 xv = *(const float2*)(x + off);
        h.x = fmaf(h.x, a.x, xv.x);
        h.y = fmaf(h.y, a.y, xv.y);
        float Hx = h.x * wx, Hy = h.y * wy;
        __nv_bfloat16 hix = __float2bfloat16_rn(Hx);
        __nv_bfloat16 hiy = __float2bfloat16_rn(Hy);
        __nv_bfloat162 hi2; hi2.x = hix; hi2.y = hiy;
        *(__nv_bfloat162*)(g_hs_hi + off) = hi2;
        float lox = Hx - __bfloat162float(hix);
        float loy = Hy - __bfloat162float(hiy);
        uchar2 lo8;
        lo8.x = (unsigned char)(signed char)q8(lox, 1.0f / SA2);
        lo8.y = (unsigned char)(signed char)q8(loy, 1.0f / SA2);
        *(uchar2*)(g_hs_lo8 + off) = lo8;
        uchar2 qq;
        qq.x = (unsigned char)(signed char)q8(Hx, 1.0f / SA3);
        qq.y = (unsigned char)(signed char)q8(Hy, 1.0f / SA3);
        *(uchar2*)(g_hs_q8 + off) = qq;
    }
}

// ---------------- Kernel 3: BC [D,O] -> BC^T splits [O,D] -----------------
__global__ void bc_transpose_split_kernel(const float* __restrict__ bc,
                                          const float* __restrict__ A) {
    __shared__ float tile[32][33];
    int o0 = blockIdx.x * 32;
    int d0 = blockIdx.y * 32;
    int tx = threadIdx.x, ty = threadIdx.y;    // 32 x 8
#pragma unroll
    for (int j = 0; j < 32; j += 8) {
        tile[ty + j][tx] = bc[(size_t)(d0 + ty + j) * OO + o0 + tx];
    }
    float ad = A[d0 + tx];
    float beta = rsqrtf(fmaf(-ad, ad, 1.0f));   // beta = 1/sqrt(1-a^2)
    __syncthreads();
#pragma unroll
    for (int j = 0; j < 32; j += 8) {
        float C = tile[tx][ty + j] * 1024.0f * beta;  // C'[d0+tx][o0+ty+j]
        size_t oi = (size_t)(o0 + ty + j) * DD + d0 + tx;
        __nv_bfloat16 Chi = __float2bfloat16_rn(C);
        g_bct_hi[oi] = Chi;
        g_bct_hi8[oi] = (unsigned char)(signed char)q8(C, 1.0f / SB2);
        float Clo = C - __bfloat162float(Chi);
        g_bct_lo8[oi] = (unsigned char)(signed char)q8(Clo, 1.0f / SB3);
    }
}

// ---------------- Kernel 4: pipelined bf16 + int8 GEMM --------------------
#define TM 128
#define TN 128
#define KT 64
#define NKC (DD / KT)        // 16 K-chunks
#define STAGES 3
#define TILE_BYTES (128 * 128)
// stage tiles: 0 = A_hi bf16, 1 = A s8 [lo8 64B | q8 64B],
//              2 = B_hi bf16, 3 = B s8 [hi8 64B | lo8 64B]
#define STAGE_BYTES (4 * TILE_BYTES)    // 64 KB
#define SM_GEMM (STAGES * STAGE_BYTES)  // 192 KB

__device__ __forceinline__ void load_stage(uint32_t stage_base, int m0, int n0,
                                           int kc, int tid) {
    int k0 = kc * KT;
#pragma unroll
    for (int i = 0; i < 16; i++) {
        int c = i * 256 + tid;
        int tile = c >> 10;
        int rem = c & 1023;
        int row = rem >> 3;
        int ch = rem & 7;
        uint32_t soff = SW128((uint32_t)(row * 128 + ch * 16));
        uint32_t daddr = stage_base + tile * TILE_BYTES + soff;
        const void* gp;
        if (tile == 0) {
            gp = g_hs_hi + (size_t)(m0 + row) * DD + k0 + ch * 8;
        } else if (tile == 1) {
            gp = (ch < 4) ? (const void*)(g_hs_lo8 + (size_t)(m0 + row) * DD + k0 + ch * 16)
                          : (const void*)(g_hs_q8  + (size_t)(m0 + row) * DD + k0 + (ch - 4) * 16);
        } else if (tile == 2) {
            gp = g_bct_hi + (size_t)(n0 + row) * DD + k0 + ch * 8;
        } else {
            gp = (ch < 4) ? (const void*)(g_bct_hi8 + (size_t)(n0 + row) * DD + k0 + ch * 16)
                          : (const void*)(g_bct_lo8 + (size_t)(n0 + row) * DD + k0 + (ch - 4) * 16);
        }
        CP_ASYNC_16(daddr, gp);
    }
}

__global__ __launch_bounds__(256, 1)
void gemm_bf16_i8_kernel(float* __restrict__ out) {
    extern __shared__ __align__(1024) char smem[];
    uint32_t sb = smem_u32(smem);
    int tid = threadIdx.x;
    int wid = tid >> 5;
    int lane = tid & 31;
    int wm = wid & 3;
    int wn = wid >> 2;
    int m0 = blockIdx.x * TM;
    int n0 = blockIdx.y * TN;

    float accf[2][8][4];
    int   acci[2][8][4];
#pragma unroll
    for (int mi = 0; mi < 2; mi++)
#pragma unroll
        for (int ni = 0; ni < 8; ni++)
#pragma unroll
            for (int c = 0; c < 4; c++) { accf[mi][ni][c] = 0.0f; acci[mi][ni][c] = 0; }

#pragma unroll
    for (int s = 0; s < STAGES - 1; s++) {
        load_stage(sb + s * STAGE_BYTES, m0, n0, s, tid);
        CP_COMMIT();
    }

    int a_row = wm * 32 + (lane & 15);
    int a_chb = ((lane >> 4) & 1) * 16;
    int b_row = wn * 64 + ((lane >> 4) & 1) * 8 + (lane & 7);
    int b_chb = ((lane >> 3) & 1) * 16;

    for (int kc = 0; kc < NKC; kc++) {
        CP_WAIT_GROUP(1);
        __syncthreads();
        if (kc + STAGES - 1 < NKC) {
            load_stage(sb + ((kc + STAGES - 1) % STAGES) * STAGE_BYTES,
                       m0, n0, kc + STAGES - 1, tid);
            CP_COMMIT();
        }

        uint32_t st = sb + (kc % STAGES) * STAGE_BYTES;
        uint32_t s_ahi = st;
        uint32_t s_a8  = st + TILE_BYTES;
        uint32_t s_bhi = st + 2 * TILE_BYTES;
        uint32_t s_b8  = st + 3 * TILE_BYTES;

        // ---- main pass: bf16 H'_hi x C'_hi ----
#pragma unroll
        for (int ks = 0; ks < KT / 16; ks++) {
            uint32_t a_hi[2][4];
            uint32_t b_hi[8][2];
#pragma unroll
            for (int mi = 0; mi < 2; mi++) {
                uint32_t off = SW128((uint32_t)((a_row + mi * 16) * 128 + ks * 32 + a_chb));
                LDSM_X4(a_hi[mi][0], a_hi[mi][1], a_hi[mi][2], a_hi[mi][3], s_ahi + off);
            }
#pragma unroll
            for (int p = 0; p < 4; p++) {
                uint32_t off = SW128((uint32_t)((b_row + p * 16) * 128 + ks * 32 + b_chb));
                uint32_t t0, t1, t2, t3;
                LDSM_X4(t0, t1, t2, t3, s_bhi + off);
                b_hi[2 * p][0] = t0; b_hi[2 * p][1] = t1;
                b_hi[2 * p + 1][0] = t2; b_hi[2 * p + 1][1] = t3;
            }
#pragma unroll
            for (int mi = 0; mi < 2; mi++)
#pragma unroll
                for (int ni = 0; ni < 8; ni++)
                    MMA_BF16(accf[mi][ni], a_hi[mi], b_hi[ni]);
        }

        // ---- int8 correction passes (shared s32 acc) ----
#pragma unroll
        for (int ks = 0; ks < KT / 32; ks++) {
            // pass2: s8(H_lo) x s8(C'_hi)
            {
                uint32_t a8[2][4];
                uint32_t b8[8][2];
#pragma unroll
                for (int mi = 0; mi < 2; mi++) {
                    uint32_t off = SW128((uint32_t)((a_row + mi * 16) * 128 + ks * 32 + a_chb));
                    LDSM_X4(a8[mi][0], a8[mi][1], a8[mi][2], a8[mi][3], s_a8 + off);
                }
#pragma unroll
                for (int p = 0; p < 4; p++) {
                    uint32_t off = SW128((uint32_t)((b_row + p * 16) * 128 + ks * 32 + b_chb));
                    uint32_t t0, t1, t2, t3;
                    LDSM_X4(t0, t1, t2, t3, s_b8 + off);
                    b8[2 * p][0] = t0; b8[2 * p][1] = t1;
                    b8[2 * p + 1][0] = t2; b8[2 * p + 1][1] = t3;
                }
#pragma unroll
                for (int mi = 0; mi < 2; mi++)
#pragma unroll
                    for (int ni = 0; ni < 8; ni++)
                        MMA_S8(acci[mi][ni], a8[mi], b8[ni]);
            }
            // pass3: s8(H') x s8(C'_lo)
            {
                uint32_t a8[2][4];
                uint32_t b8[8][2];
#pragma unroll
                for (int mi = 0; mi < 2; mi++) {
                    uint32_t off = SW128((uint32_t)((a_row + mi * 16) * 128 + 64 + ks * 32 + a_chb));
                    LDSM_X4(a8[mi][0], a8[mi][1], a8[mi][2], a8[mi][3], s_a8 + off);
                }
#pragma unroll
                for (int p = 0; p < 4; p++) {
                    uint32_t off = SW128((uint32_t)((b_row + p * 16) * 128 + 64 + ks * 32 + b_chb));
                    uint32_t t0, t1, t2, t3;
                    LDSM_X4(t0, t1, t2, t3, s_b8 + off);
                    b8[2 * p][0] = t0; b8[2 * p][1] = t1;
                    b8[2 * p + 1][0] = t2; b8[2 * p + 1][1] = t3;
                }
#pragma unroll
                for (int mi = 0; mi < 2; mi++)
#pragma unroll
                    for (int ni = 0; ni < 8; ni++)
                        MMA_S8(acci[mi][ni], a8[mi], b8[ni]);
            }
        }
    }

    // epilogue: out = (accf + CORR*acci) / 8192
#pragma unroll
    for (int mi = 0; mi < 2; mi++) {
#pragma unroll
        for (int ni = 0; ni < 8; ni++) {
            int row = m0 + wm * 32 + mi * 16 + (lane >> 2);
            int col = n0 + wn * 64 + ni * 8 + 2 * (lane & 3);
            float v0 = fmaf((float)acci[mi][ni][0], CORR, accf[mi][ni][0]) * OUT_SCALE;
            float v1 = fmaf((float)acci[mi][ni][1], CORR, accf[mi][ni][1]) * OUT_SCALE;
            float v2 = fmaf((float)acci[mi][ni][2], CORR, accf[mi][ni][2]) * OUT_SCALE;
            float v3 = fmaf((float)acci[mi][ni][3], CORR, accf[mi][ni][3]) * OUT_SCALE;
            *(float2*)(out + (size_t)row * OO + col) = make_float2(v0, v1);
            *(float2*)(out + (size_t)(row + 8) * OO + col) = make_float2(v2, v3);
        }
    }
}

// ---------------- launch --------------------------------------------------
extern "C" void kernel_launch(void* const* d_in, const int* in_sizes, int n_in,
                              void* d_out, int out_size) {
    const float* x  = (const float*)d_in[0];   // [B, S, D]
    const float* A  = (const float*)d_in[1];   // [D]
    const float* BC = (const float*)d_in[2];   // [D, O]
    float* out = (float*)d_out;                // [B, S, O]
    (void)in_sizes; (void)n_in; (void)out_size;

    int scan_threads = BB * NCH * DD / 2;      // 65536
    scan_carry_kernel<<<scan_threads / 128, 128>>>(x, A);
    scan_emit_kernel<<<scan_threads / 128, 128>>>(x, A);
    bc_transpose_split_kernel<<<dim3(OO / 32, DD / 32), dim3(32, 8)>>>(BC, A);

    cudaFuncSetAttribute(gemm_bf16_i8_kernel,
                         cudaFuncAttributeMaxDynamicSharedMemorySize, SM_GEMM);
    dim3 grid((BB * SS) / TM, OO / TN);        // 128 x 8
    gemm_bf16_i8_kernel<<<grid, 256, SM_GEMM>>>(out);
}

// round 6
// speedup vs baseline: 4.8333x; 4.8333x over previous
#include <cuda_runtime.h>
#include <cuda_fp16.h>
#include <cstdint>

// Problem shape (fixed by dataset)
#define BB 8
#define SS 2048
#define DD 1024
#define OO 1024
#define LCH 128           // scan chunk length
#define NCH (SS / LCH)    // 16 chunks

// C' = 1024*BC ; out = acc / 1024
#define OUT_SCALE (1.0f / 1024.0f)

// ---------------- device scratch (no allocations allowed) ----------------
__device__ float   g_carry[BB * NCH * DD];            // 512 KB
__device__ __half  g_hs[(size_t)BB * SS * DD];        // 32 MB  fp16(h)
__device__ __half  g_bct[(size_t)OO * DD];            // 2 MB   fp16(1024*BC^T)

// ---------------- helpers --------------------------------------------------
__device__ __forceinline__ uint32_t smem_u32(const void* p) {
    uint32_t a;
    asm("{ .reg .u64 t; cvta.to.shared.u64 t, %1; cvt.u32.u64 %0, t; }"
        : "=r"(a) : "l"(p));
    return a;
}

#define SW128(off) ((off) ^ (((off) >> 3) & 0x70))

#define CP_ASYNC_16(dst_smem, src_gmem) \
    asm volatile("cp.async.cg.shared.global [%0], [%1], 16;" \
                 :: "r"(dst_smem), "l"(src_gmem) : "memory")
#define CP_COMMIT() asm volatile("cp.async.commit_group;" ::: "memory")
#define CP_WAIT_GROUP(n) asm volatile("cp.async.wait_group %0;" :: "n"(n) : "memory")

#define LDSM_X4(r0, r1, r2, r3, addr) \
    asm volatile("ldmatrix.sync.aligned.m8n8.x4.shared.b16 {%0,%1,%2,%3}, [%4];" \
                 : "=r"(r0), "=r"(r1), "=r"(r2), "=r"(r3) : "r"(addr))

#define MMA_F16(c, a, b) \
    asm volatile("mma.sync.aligned.m16n8k16.row.col.f32.f16.f16.f32 " \
                 "{%0,%1,%2,%3}, {%4,%5,%6,%7}, {%8,%9}, {%0,%1,%2,%3};" \
                 : "+f"((c)[0]), "+f"((c)[1]), "+f"((c)[2]), "+f"((c)[3]) \
                 : "r"((a)[0]), "r"((a)[1]), "r"((a)[2]), "r"((a)[3]), \
                   "r"((b)[0]), "r"((b)[1]))

// ---------------- Kernel 1: per-chunk carries (float2/thread) -------------
__global__ void scan_carry_kernel(const float* __restrict__ x,
                                  const float* __restrict__ A) {
    int idx = blockIdx.x * blockDim.x + threadIdx.x;   // B*NCH*DD/2 threads
    int d = (idx & (DD / 2 - 1)) * 2;
    int chunk = (idx >> 9) & (NCH - 1);
    int b = idx >> 13;
    float2 a = *(const float2*)(A + d);
    const float* xp = x + ((size_t)(b * SS + chunk * LCH)) * DD + d;
    float2 h = make_float2(0.0f, 0.0f);
#pragma unroll 8
    for (int i = 0; i < LCH; i++) {
        float2 xv = *(const float2*)(xp + (size_t)i * DD);
        h.x = fmaf(h.x, a.x, xv.x);
        h.y = fmaf(h.y, a.y, xv.y);
    }
    *(float2*)(g_carry + (size_t)((b * NCH + chunk) * DD) + d) = h;
}

// ---------------- Kernel 2: carry-corrected emit -> fp16 ------------------
__global__ void scan_emit_kernel(const float* __restrict__ x,
                                 const float* __restrict__ A) {
    int idx = blockIdx.x * blockDim.x + threadIdx.x;
    int d = (idx & (DD / 2 - 1)) * 2;
    int chunk = (idx >> 9) & (NCH - 1);
    int b = idx >> 13;
    float2 a = *(const float2*)(A + d);
    float2 aL = a;
#pragma unroll
    for (int s = 0; s < 7; s++) { aL.x *= aL.x; aL.y *= aL.y; }   // a^128
    float2 h = make_float2(0.0f, 0.0f);
    for (int j = 0; j < chunk; j++) {
        float2 cv = *(const float2*)(g_carry + (size_t)((b * NCH + j) * DD) + d);
        h.x = fmaf(h.x, aL.x, cv.x);
        h.y = fmaf(h.y, aL.y, cv.y);
    }
    size_t base = ((size_t)(b * SS + chunk * LCH)) * DD + d;
#pragma unroll 4
    for (int i = 0; i < LCH; i++) {
        size_t off = base + (size_t)i * DD;
        float2 xv = *(const float2*)(x + off);
        h.x = fmaf(h.x, a.x, xv.x);
        h.y = fmaf(h.y, a.y, xv.y);
        *(__half2*)(g_hs + off) = __float22half2_rn(h);
    }
}

// ---------------- Kernel 3: BC [D,O] -> fp16 1024*BC^T [O,D] --------------
__global__ void bc_transpose_kernel(const float* __restrict__ bc) {
    __shared__ float tile[32][33];
    int o0 = blockIdx.x * 32;
    int d0 = blockIdx.y * 32;
    int tx = threadIdx.x, ty = threadIdx.y;    // 32 x 8
#pragma unroll
    for (int j = 0; j < 32; j += 8) {
        tile[ty + j][tx] = bc[(size_t)(d0 + ty + j) * OO + o0 + tx];
    }
    __syncthreads();
#pragma unroll
    for (int j = 0; j < 32; j += 8) {
        float C = tile[tx][ty + j] * 1024.0f;  // C'[d0+tx][o0+ty+j]
        size_t oi = (size_t)(o0 + ty + j) * DD + d0 + tx;
        g_bct[oi] = __float2half_rn(C);
    }
}

// ---------------- Kernel 4: pipelined fp16 HMMA GEMM ----------------------
// acc[r, n] = sum_k h[r, k] * C'[k, n] ; out = acc / 1024
#define TM 128
#define TN 128
#define KT 64
#define NKC (DD / KT)        // 16 K-chunks
#define STAGES 3
#define TILE_BYTES (128 * 128)          // one operand tile: 128 rows x 128B
#define STAGE_BYTES (2 * TILE_BYTES)    // A, B  = 32 KB
#define SM_GEMM (STAGES * STAGE_BYTES)  // 96 KB  -> 2 CTAs/SM

__device__ __forceinline__ void load_stage(uint32_t stage_base, int m0, int n0,
                                           int kc, int tid) {
    int k0 = kc * KT;
#pragma unroll
    for (int i = 0; i < 8; i++) {
        int c = i * 256 + tid;          // 0..2047
        int tile = c >> 10;             // 0:A 1:B
        int rem = c & 1023;
        int row = rem >> 3;
        int ch = rem & 7;
        uint32_t soff = SW128((uint32_t)(row * 128 + ch * 16));
        uint32_t daddr = stage_base + tile * TILE_BYTES + soff;
        const __half* gp = (tile == 0)
            ? g_hs  + (size_t)(m0 + row) * DD + k0 + ch * 8
            : g_bct + (size_t)(n0 + row) * DD + k0 + ch * 8;
        CP_ASYNC_16(daddr, gp);
    }
}

__global__ __launch_bounds__(256, 2)
void gemm_f16_kernel(float* __restrict__ out) {
    extern __shared__ __align__(1024) char smem[];
    uint32_t sb = smem_u32(smem);
    int tid = threadIdx.x;
    int wid = tid >> 5;
    int lane = tid & 31;
    int wm = wid & 3;           // 4 warps along M
    int wn = wid >> 2;          // 2 warps along N
    int m0 = blockIdx.x * TM;
    int n0 = blockIdx.y * TN;

    float acc[2][8][4];
#pragma unroll
    for (int mi = 0; mi < 2; mi++)
#pragma unroll
        for (int ni = 0; ni < 8; ni++)
#pragma unroll
            for (int c = 0; c < 4; c++) acc[mi][ni][c] = 0.0f;

#pragma unroll
    for (int s = 0; s < STAGES - 1; s++) {
        load_stage(sb + s * STAGE_BYTES, m0, n0, s, tid);
        CP_COMMIT();
    }

    int a_row = wm * 32 + (lane & 15);
    int a_chb = ((lane >> 4) & 1) * 16;
    int b_row = wn * 64 + ((lane >> 4) & 1) * 8 + (lane & 7);
    int b_chb = ((lane >> 3) & 1) * 16;

    for (int kc = 0; kc < NKC; kc++) {
        CP_WAIT_GROUP(1);
        __syncthreads();
        if (kc + STAGES - 1 < NKC) {
            load_stage(sb + ((kc + STAGES - 1) % STAGES) * STAGE_BYTES,
                       m0, n0, kc + STAGES - 1, tid);
            CP_COMMIT();
        }

        uint32_t st = sb + (kc % STAGES) * STAGE_BYTES;
        uint32_t s_a = st;
        uint32_t s_b = st + TILE_BYTES;

#pragma unroll
        for (int ks = 0; ks < KT / 16; ks++) {
            uint32_t af[2][4];
            uint32_t bf[8][2];
#pragma unroll
            for (int mi = 0; mi < 2; mi++) {
                uint32_t off = SW128((uint32_t)((a_row + mi * 16) * 128 + ks * 32 + a_chb));
                LDSM_X4(af[mi][0], af[mi][1], af[mi][2], af[mi][3], s_a + off);
            }
#pragma unroll
            for (int p = 0; p < 4; p++) {
                uint32_t off = SW128((uint32_t)((b_row + p * 16) * 128 + ks * 32 + b_chb));
                uint32_t t0, t1, t2, t3;
                LDSM_X4(t0, t1, t2, t3, s_b + off);
                bf[2 * p][0] = t0; bf[2 * p][1] = t1;
                bf[2 * p + 1][0] = t2; bf[2 * p + 1][1] = t3;
            }
#pragma unroll
            for (int mi = 0; mi < 2; mi++)
#pragma unroll
                for (int ni = 0; ni < 8; ni++)
                    MMA_F16(acc[mi][ni], af[mi], bf[ni]);
        }
    }

    // epilogue: scale and store
#pragma unroll
    for (int mi = 0; mi < 2; mi++) {
#pragma unroll
        for (int ni = 0; ni < 8; ni++) {
            int row = m0 + wm * 32 + mi * 16 + (lane >> 2);
            int col = n0 + wn * 64 + ni * 8 + 2 * (lane & 3);
            float2 v0 = make_float2(acc[mi][ni][0] * OUT_SCALE,
                                    acc[mi][ni][1] * OUT_SCALE);
            float2 v1 = make_float2(acc[mi][ni][2] * OUT_SCALE,
                                    acc[mi][ni][3] * OUT_SCALE);
            *(float2*)(out + (size_t)row * OO + col) = v0;
            *(float2*)(out + (size_t)(row + 8) * OO + col) = v1;
        }
    }
}

// ---------------- launch --------------------------------------------------
extern "C" void kernel_launch(void* const* d_in, const int* in_sizes, int n_in,
                              void* d_out, int out_size) {
    const float* x  = (const float*)d_in[0];   // [B, S, D]
    const float* A  = (const float*)d_in[1];   // [D]
    const float* BC = (const float*)d_in[2];   // [D, O]
    float* out = (float*)d_out;                // [B, S, O]
    (void)in_sizes; (void)n_in; (void)out_size;

    int scan_threads = BB * NCH * DD / 2;      // 65536
    scan_carry_kernel<<<scan_threads / 128, 128>>>(x, A);
    scan_emit_kernel<<<scan_threads / 128, 128>>>(x, A);
    bc_transpose_kernel<<<dim3(OO / 32, DD / 32), dim3(32, 8)>>>(BC);

    cudaFuncSetAttribute(gemm_f16_kernel,
                         cudaFuncAttributeMaxDynamicSharedMemorySize, SM_GEMM);
    dim3 grid((BB * SS) / TM, OO / TN);        // 128 x 8
    gemm_f16_kernel<<<grid, 256, SM_GEMM>>>(out);
}

// round 7
// speedup vs baseline: 4.9112x; 1.0161x over previous
#include <cuda_runtime.h>
#include <cuda_fp16.h>
#include <cstdint>

// Problem shape (fixed by dataset)
#define BB 8
#define SS 2048
#define DD 1024
#define OO 1024
#define LCH 128           // scan chunk length
#define NCH (SS / LCH)    // 16 chunks

// ---------------- device scratch (no allocations allowed) ----------------
__device__ float   g_carry[BB * NCH * DD];            // 512 KB
__device__ __half  g_hs[(size_t)BB * SS * DD];        // 32 MB  fp16(h)
__device__ __half  g_bct[(size_t)OO * DD];            // 2 MB   fp16(BC^T)

// ---------------- helpers --------------------------------------------------
__device__ __forceinline__ uint32_t smem_u32(const void* p) {
    uint32_t a;
    asm("{ .reg .u64 t; cvta.to.shared.u64 t, %1; cvt.u32.u64 %0, t; }"
        : "=r"(a) : "l"(p));
    return a;
}

#define SW128(off) ((off) ^ (((off) >> 3) & 0x70))

#define CP_ASYNC_16(dst_smem, src_gmem) \
    asm volatile("cp.async.cg.shared.global [%0], [%1], 16;" \
                 :: "r"(dst_smem), "l"(src_gmem) : "memory")
#define CP_COMMIT() asm volatile("cp.async.commit_group;" ::: "memory")
#define CP_WAIT_GROUP(n) asm volatile("cp.async.wait_group %0;" :: "n"(n) : "memory")

#define LDSM_X4(r0, r1, r2, r3, addr) \
    asm volatile("ldmatrix.sync.aligned.m8n8.x4.shared.b16 {%0,%1,%2,%3}, [%4];" \
                 : "=r"(r0), "=r"(r1), "=r"(r2), "=r"(r3) : "r"(addr))

#define MMA_F16(c, a, b) \
    asm volatile("mma.sync.aligned.m16n8k16.row.col.f32.f16.f16.f32 " \
                 "{%0,%1,%2,%3}, {%4,%5,%6,%7}, {%8,%9}, {%0,%1,%2,%3};" \
                 : "+f"((c)[0]), "+f"((c)[1]), "+f"((c)[2]), "+f"((c)[3]) \
                 : "r"((a)[0]), "r"((a)[1]), "r"((a)[2]), "r"((a)[3]), \
                   "r"((b)[0]), "r"((b)[1]))

// ---------------- Kernel 1: per-chunk carries (float2/thread) -------------
__global__ void scan_carry_kernel(const float* __restrict__ x,
                                  const float* __restrict__ A) {
    int idx = blockIdx.x * blockDim.x + threadIdx.x;   // B*NCH*DD/2 threads
    int d = (idx & (DD / 2 - 1)) * 2;
    int chunk = (idx >> 9) & (NCH - 1);
    int b = idx >> 13;
    float2 a = *(const float2*)(A + d);
    const float* xp = x + ((size_t)(b * SS + chunk * LCH)) * DD + d;
    float2 h = make_float2(0.0f, 0.0f);
#pragma unroll 8
    for (int i = 0; i < LCH; i++) {
        float2 xv = *(const float2*)(xp + (size_t)i * DD);
        h.x = fmaf(h.x, a.x, xv.x);
        h.y = fmaf(h.y, a.y, xv.y);
    }
    *(float2*)(g_carry + (size_t)((b * NCH + chunk) * DD) + d) = h;
}

// ---------------- Kernel 2: carry-corrected emit -> fp16 ------------------
__global__ void scan_emit_kernel(const float* __restrict__ x,
                                 const float* __restrict__ A) {
    int idx = blockIdx.x * blockDim.x + threadIdx.x;
    int d = (idx & (DD / 2 - 1)) * 2;
    int chunk = (idx >> 9) & (NCH - 1);
    int b = idx >> 13;
    float2 a = *(const float2*)(A + d);
    float2 aL = a;
#pragma unroll
    for (int s = 0; s < 7; s++) { aL.x *= aL.x; aL.y *= aL.y; }   // a^128
    float2 h = make_float2(0.0f, 0.0f);
    for (int j = 0; j < chunk; j++) {
        float2 cv = *(const float2*)(g_carry + (size_t)((b * NCH + j) * DD) + d);
        h.x = fmaf(h.x, aL.x, cv.x);
        h.y = fmaf(h.y, aL.y, cv.y);
    }
    size_t base = ((size_t)(b * SS + chunk * LCH)) * DD + d;
#pragma unroll 8
    for (int i = 0; i < LCH; i++) {
        size_t off = base + (size_t)i * DD;
        float2 xv = *(const float2*)(x + off);
        h.x = fmaf(h.x, a.x, xv.x);
        h.y = fmaf(h.y, a.y, xv.y);
        *(__half2*)(g_hs + off) = __float22half2_rn(h);
    }
}

// ---------------- Kernel 3: BC [D,O] -> fp16 BC^T [O,D] -------------------
__global__ void bc_transpose_kernel(const float* __restrict__ bc) {
    __shared__ float tile[32][33];
    int o0 = blockIdx.x * 32;
    int d0 = blockIdx.y * 32;
    int tx = threadIdx.x, ty = threadIdx.y;    // 32 x 8
#pragma unroll
    for (int j = 0; j < 32; j += 8) {
        tile[ty + j][tx] = bc[(size_t)(d0 + ty + j) * OO + o0 + tx];
    }
    __syncthreads();
#pragma unroll
    for (int j = 0; j < 32; j += 8) {
        size_t oi = (size_t)(o0 + ty + j) * DD + d0 + tx;
        g_bct[oi] = __float2half_rn(tile[tx][ty + j]);
    }
}

// ---------------- Kernel 4: pipelined fp16 HMMA GEMM ----------------------
// out[r, n] = sum_k h[r, k] * BC[k, n]
#define TM 128
#define TN 128
#define KT 64
#define NKC (DD / KT)        // 16 K-chunks
#define STAGES 3
#define TILE_BYTES (128 * 128)          // one operand tile: 128 rows x 128B
#define STAGE_BYTES (2 * TILE_BYTES)    // A, B  = 32 KB
#define SM_GEMM (STAGES * STAGE_BYTES)  // 96 KB  -> 2 CTAs/SM

__device__ __forceinline__ void load_stage(uint32_t stage_base, int m0, int n0,
                                           int kc, int tid) {
    int k0 = kc * KT;
#pragma unroll
    for (int i = 0; i < 8; i++) {
        int c = i * 256 + tid;          // 0..2047
        int tile = c >> 10;             // 0:A 1:B
        int rem = c & 1023;
        int row = rem >> 3;
        int ch = rem & 7;
        uint32_t soff = SW128((uint32_t)(row * 128 + ch * 16));
        uint32_t daddr = stage_base + tile * TILE_BYTES + soff;
        const __half* gp = (tile == 0)
            ? g_hs  + (size_t)(m0 + row) * DD + k0 + ch * 8
            : g_bct + (size_t)(n0 + row) * DD + k0 + ch * 8;
        CP_ASYNC_16(daddr, gp);
    }
}

__device__ __forceinline__ void ldsm_a_frag(uint32_t s_a, int a_row, int a_chb,
                                            int ks, uint32_t af[2][4]) {
#pragma unroll
    for (int mi = 0; mi < 2; mi++) {
        uint32_t off = SW128((uint32_t)((a_row + mi * 16) * 128 + ks * 32 + a_chb));
        LDSM_X4(af[mi][0], af[mi][1], af[mi][2], af[mi][3], s_a + off);
    }
}

__device__ __forceinline__ void ldsm_b_frag(uint32_t s_b, int b_row, int b_chb,
                                            int ks, uint32_t bf[8][2]) {
#pragma unroll
    for (int p = 0; p < 4; p++) {
        uint32_t off = SW128((uint32_t)((b_row + p * 16) * 128 + ks * 32 + b_chb));
        uint32_t t0, t1, t2, t3;
        LDSM_X4(t0, t1, t2, t3, s_b + off);
        bf[2 * p][0] = t0; bf[2 * p][1] = t1;
        bf[2 * p + 1][0] = t2; bf[2 * p + 1][1] = t3;
    }
}

__global__ __launch_bounds__(256, 2)
void gemm_f16_kernel(float* __restrict__ out) {
    extern __shared__ __align__(1024) char smem[];
    uint32_t sb = smem_u32(smem);
    int tid = threadIdx.x;
    int wid = tid >> 5;
    int lane = tid & 31;
    int wm = wid & 3;           // 4 warps along M
    int wn = wid >> 2;          // 2 warps along N
    int m0 = blockIdx.x * TM;
    int n0 = blockIdx.y * TN;

    float acc[2][8][4];
#pragma unroll
    for (int mi = 0; mi < 2; mi++)
#pragma unroll
        for (int ni = 0; ni < 8; ni++)
#pragma unroll
            for (int c = 0; c < 4; c++) acc[mi][ni][c] = 0.0f;

#pragma unroll
    for (int s = 0; s < STAGES - 1; s++) {
        load_stage(sb + s * STAGE_BYTES, m0, n0, s, tid);
        CP_COMMIT();
    }

    int a_row = wm * 32 + (lane & 15);
    int a_chb = ((lane >> 4) & 1) * 16;
    int b_row = wn * 64 + ((lane >> 4) & 1) * 8 + (lane & 7);
    int b_chb = ((lane >> 3) & 1) * 16;

    uint32_t af[2][2][4];       // double-buffered A fragments
    uint32_t bf[2][8][2];       // double-buffered B fragments

    for (int kc = 0; kc < NKC; kc++) {
        CP_WAIT_GROUP(1);
        __syncthreads();

        uint32_t st = sb + (kc % STAGES) * STAGE_BYTES;
        uint32_t s_a = st;
        uint32_t s_b = st + TILE_BYTES;

        // preload fragments for ks=0, then issue next stage's cp.asyncs
        ldsm_a_frag(s_a, a_row, a_chb, 0, af[0]);
        ldsm_b_frag(s_b, b_row, b_chb, 0, bf[0]);

        if (kc + STAGES - 1 < NKC) {
            load_stage(sb + ((kc + STAGES - 1) % STAGES) * STAGE_BYTES,
                       m0, n0, kc + STAGES - 1, tid);
            CP_COMMIT();
        }

#pragma unroll
        for (int ks = 0; ks < KT / 16; ks++) {
            int cur = ks & 1;
            if (ks < KT / 16 - 1) {
                ldsm_a_frag(s_a, a_row, a_chb, ks + 1, af[cur ^ 1]);
                ldsm_b_frag(s_b, b_row, b_chb, ks + 1, bf[cur ^ 1]);
            }
#pragma unroll
            for (int mi = 0; mi < 2; mi++)
#pragma unroll
                for (int ni = 0; ni < 8; ni++)
                    MMA_F16(acc[mi][ni], af[cur][mi], bf[cur][ni]);
        }
    }

    // epilogue
#pragma unroll
    for (int mi = 0; mi < 2; mi++) {
#pragma unroll
        for (int ni = 0; ni < 8; ni++) {
            int row = m0 + wm * 32 + mi * 16 + (lane >> 2);
            int col = n0 + wn * 64 + ni * 8 + 2 * (lane & 3);
            float2 v0 = make_float2(acc[mi][ni][0], acc[mi][ni][1]);
            float2 v1 = make_float2(acc[mi][ni][2], acc[mi][ni][3]);
            *(float2*)(out + (size_t)row * OO + col) = v0;
            *(float2*)(out + (size_t)(row + 8) * OO + col) = v1;
        }
    }
}

// ---------------- launch --------------------------------------------------
extern "C" void kernel_launch(void* const* d_in, const int* in_sizes, int n_in,
                              void* d_out, int out_size) {
    const float* x  = (const float*)d_in[0];   // [B, S, D]
    const float* A  = (const float*)d_in[1];   // [D]
    const float* BC = (const float*)d_in[2];   // [D, O]
    float* out = (float*)d_out;                // [B, S, O]
    (void)in_sizes; (void)n_in; (void)out_size;

    int scan_threads = BB * NCH * DD / 2;      // 65536
    scan_carry_kernel<<<scan_threads / 128, 128>>>(x, A);
    scan_emit_kernel<<<scan_threads / 128, 128>>>(x, A);
    bc_transpose_kernel<<<dim3(OO / 32, DD / 32), dim3(32, 8)>>>(BC);

    cudaFuncSetAttribute(gemm_f16_kernel,
                         cudaFuncAttributeMaxDynamicSharedMemorySize, SM_GEMM);
    dim3 grid((BB * SS) / TM, OO / TN);        // 128 x 8
    gemm_f16_kernel<<<grid, 256, SM_GEMM>>>(out);
}